// round 1
// baseline (speedup 1.0000x reference)
#include <cuda_runtime.h>
#include <math.h>

#define Bsz 8
#define Sl  1024
#define Dm  512
#define Hn  8
#define DQn 64
#define DVn 64
#define Pn  32
#define BH  (Bsz*Hn)   // 64

// ---------------- scratch (__device__ globals: allocation-free) ----------------
__device__ float g_xn  [Bsz*Sl*Dm];          // layernormed x    [8192,512]
__device__ float g_k   [BH*Sl*DQn];          // keys   [B,H,S,DQ]
__device__ float g_v   [BH*Sl*DVn];          // values [B,H,S,DV]
__device__ float g_bias[Sl*Sl];              // (pos@wp + bp)/8  [S,S]
__device__ float g_attn[Bsz*Sl*Hn*DVn];      // attention output [B,S,H*DV]
__device__ float g_seq_fb[Bsz*Sl*Dm];        // fallback seq buffer
__device__ float g_probs_fb[(size_t)BH*Sl*Sl]; // fallback probs buffer

// ---------------- LayerNorm: one block per row ----------------
__global__ void ln_kernel(const float* __restrict__ x, const float* __restrict__ g,
                          const float* __restrict__ bta, float* __restrict__ xn) {
    __shared__ float rs[4], rs2[4];
    int row = blockIdx.x;                // 8192 rows
    int tid = threadIdx.x;               // 128 threads, 4 floats each
    const float4* xr = (const float4*)(x + (size_t)row * Dm);
    float4 v = xr[tid];
    float s  = v.x + v.y + v.z + v.w;
    float s2 = v.x*v.x + v.y*v.y + v.z*v.z + v.w*v.w;
    #pragma unroll
    for (int o = 16; o > 0; o >>= 1) {
        s  += __shfl_xor_sync(0xffffffffu, s,  o);
        s2 += __shfl_xor_sync(0xffffffffu, s2, o);
    }
    if ((tid & 31) == 0) { rs[tid >> 5] = s; rs2[tid >> 5] = s2; }
    __syncthreads();
    s  = rs[0]  + rs[1]  + rs[2]  + rs[3];
    s2 = rs2[0] + rs2[1] + rs2[2] + rs2[3];
    float mu  = s * (1.0f / Dm);
    float var = s2 * (1.0f / Dm) - mu * mu;
    float r   = rsqrtf(var + 1e-5f);
    float4 gv = ((const float4*)g)[tid];
    float4 bv = ((const float4*)bta)[tid];
    float4 o;
    o.x = (v.x - mu) * r * gv.x + bv.x;
    o.y = (v.y - mu) * r * gv.y + bv.y;
    o.z = (v.z - mu) * r * gv.z + bv.z;
    o.w = (v.w - mu) * r * gv.w + bv.w;
    ((float4*)(xn + (size_t)row * Dm))[tid] = o;
}

// ---------------- bias = (pos @ wp + bp) / sqrt(DQ) ----------------
__global__ void bias_kernel(const float* __restrict__ pos, const float* __restrict__ wp,
                            const float* __restrict__ bp, float* __restrict__ biasS) {
    __shared__ float w[Pn];
    int tid = threadIdx.x;
    if (tid < Pn) w[tid] = wp[tid];
    __syncthreads();
    int idx = blockIdx.x * blockDim.x + tid;   // 1M entries
    const float4* p4 = (const float4*)(pos + (size_t)idx * Pn);
    float acc = 0.f;
    #pragma unroll
    for (int i = 0; i < 8; i++) {
        float4 t = p4[i];
        acc += t.x * w[4*i] + t.y * w[4*i+1] + t.z * w[4*i+2] + t.w * w[4*i+3];
    }
    biasS[idx] = (acc + bp[0]) * 0.125f;   // /sqrt(DQ)=8 folded in
}

// ---------------- projection GEMM: xn[8192,512] @ W[512,512] + b -> [B,H,S,64] ----------------
__global__ void gemm_proj(const float* __restrict__ A, const float* __restrict__ W,
                          const float* __restrict__ bias, float* __restrict__ outp) {
    __shared__ float As[16][68];   // As[k][m]
    __shared__ float Bs[16][64];   // Bs[k][n]
    const int K = 512;
    int m0 = blockIdx.y * 64;
    int n0 = blockIdx.x * 64;
    int tid = threadIdx.x;         // 256
    int tx = tid % 16, ty = tid / 16;
    float acc[4][4] = {};
    for (int k0 = 0; k0 < K; k0 += 16) {
        {
            int kk = tid % 16, mm = tid / 16;
            #pragma unroll
            for (int i = 0; i < 4; i++)
                As[kk][mm + 16*i] = A[(size_t)(m0 + mm + 16*i) * K + k0 + kk];
        }
        {
            int nn = tid % 64, kk = tid / 64;
            #pragma unroll
            for (int i = 0; i < 4; i++)
                Bs[kk + 4*i][nn] = W[(size_t)(k0 + kk + 4*i) * Dm + n0 + nn];
        }
        __syncthreads();
        #pragma unroll
        for (int kk = 0; kk < 16; kk++) {
            float4 a = *(const float4*)&As[kk][ty*4];
            float4 b = *(const float4*)&Bs[kk][tx*4];
            float av[4] = {a.x, a.y, a.z, a.w};
            float bv[4] = {b.x, b.y, b.z, b.w};
            #pragma unroll
            for (int i = 0; i < 4; i++)
                #pragma unroll
                for (int j = 0; j < 4; j++)
                    acc[i][j] += av[i] * bv[j];
        }
        __syncthreads();
    }
    #pragma unroll
    for (int i = 0; i < 4; i++) {
        int m  = m0 + ty*4 + i;
        int bb = m >> 10, ss = m & 1023;
        #pragma unroll
        for (int j = 0; j < 4; j++) {
            int n  = n0 + tx*4 + j;
            int hh = n >> 6, dd = n & 63;
            outp[(((size_t)(bb*Hn + hh) * Sl + ss) << 6) + dd] = acc[i][j] + bias[n];
        }
    }
}

// ---------------- scores: logits[b,h,q,k] = (k_q . k_k)*c1 + bias[q,k]; mask ----------------
__global__ void scores_kernel(const float* __restrict__ Kmat, const float* __restrict__ biasS,
                              const float* __restrict__ wp, const int* __restrict__ lens,
                              float* __restrict__ probs) {
    __shared__ float As[64][65];  // As[d][q]
    __shared__ float Bs[64][65];  // Bs[d][k]
    __shared__ float s_c1;
    int z  = blockIdx.z;                    // 0..63  (b*8+h)
    int q0 = blockIdx.y * 64;
    int k0 = blockIdx.x * 64;
    const float* Kb = Kmat + (size_t)z * Sl * DQn;
    int tid = threadIdx.x;                  // 256
    if (tid == 0) {
        float sw = 0.f;
        #pragma unroll
        for (int i = 0; i < Pn; i++) sw += wp[i];
        s_c1 = sw / (sqrtf(8.0f) * 8.0f);   // swp / (sqrt(H)*sqrt(DQ))
    }
    {
        int dd = tid % 64, qq = tid / 64;   // qq 0..3
        #pragma unroll
        for (int i = 0; i < 16; i++) {
            As[dd][qq + 4*i] = Kb[(size_t)(q0 + qq + 4*i) * DQn + dd];
            Bs[dd][qq + 4*i] = Kb[(size_t)(k0 + qq + 4*i) * DQn + dd];
        }
    }
    __syncthreads();
    int tx = tid % 16, ty = tid / 16;
    float acc[4][4] = {};
    #pragma unroll 16
    for (int d = 0; d < 64; d++) {
        float av[4], bv[4];
        #pragma unroll
        for (int i = 0; i < 4; i++) av[i] = As[d][ty*4 + i];
        #pragma unroll
        for (int j = 0; j < 4; j++) bv[j] = Bs[d][tx*4 + j];
        #pragma unroll
        for (int i = 0; i < 4; i++)
            #pragma unroll
            for (int j = 0; j < 4; j++)
                acc[i][j] += av[i] * bv[j];
    }
    float c1 = s_c1;
    int b   = z >> 3;
    int len = lens[b];
    #pragma unroll
    for (int i = 0; i < 4; i++) {
        int q = q0 + ty*4 + i;
        #pragma unroll
        for (int j = 0; j < 4; j++) {
            int kk = k0 + tx*4 + j;
            float val = (kk < len) ? (acc[i][j] * c1 + biasS[q * Sl + kk]) : -INFINITY;
            probs[((size_t)z * Sl + q) * Sl + kk] = val;
        }
    }
}

// ---------------- in-place row softmax over probs ----------------
__global__ void softmax_kernel(float* __restrict__ probs) {
    __shared__ float red[8];
    size_t row = blockIdx.x;                // 65536 rows
    float* p = probs + row * Sl;
    int tid = threadIdx.x;                  // 256, 4 floats each
    float4 v = ((const float4*)p)[tid];
    float m = fmaxf(fmaxf(v.x, v.y), fmaxf(v.z, v.w));
    #pragma unroll
    for (int o = 16; o > 0; o >>= 1) m = fmaxf(m, __shfl_xor_sync(0xffffffffu, m, o));
    if ((tid & 31) == 0) red[tid >> 5] = m;
    __syncthreads();
    m = red[0];
    #pragma unroll
    for (int i = 1; i < 8; i++) m = fmaxf(m, red[i]);
    float4 e;
    e.x = expf(v.x - m); e.y = expf(v.y - m);
    e.z = expf(v.z - m); e.w = expf(v.w - m);
    float s = e.x + e.y + e.z + e.w;
    #pragma unroll
    for (int o = 16; o > 0; o >>= 1) s += __shfl_xor_sync(0xffffffffu, s, o);
    __syncthreads();                        // all max reads done before reuse
    if ((tid & 31) == 0) red[tid >> 5] = s;
    __syncthreads();
    float tot = red[0];
    #pragma unroll
    for (int i = 1; i < 8; i++) tot += red[i];
    float inv = 1.0f / tot;
    float4 o4 = make_float4(e.x * inv, e.y * inv, e.z * inv, e.w * inv);
    ((float4*)p)[tid] = o4;
}

// ---------------- PV GEMM: per head, probs[S,S] @ v[S,64] -> attn [B,S,H*DV] ----------------
__global__ void gemm_pv(const float* __restrict__ probs, const float* __restrict__ V,
                        float* __restrict__ outp) {
    __shared__ float As[16][68];
    __shared__ float Bs[16][64];
    int z  = blockIdx.z;                    // 0..63
    int m0 = blockIdx.y * 64;               // q tile
    const float* A = probs + (size_t)z * Sl * Sl;
    const float* Bm = V + (size_t)z * Sl * DVn;
    int tid = threadIdx.x;
    int tx = tid % 16, ty = tid / 16;
    float acc[4][4] = {};
    for (int k0 = 0; k0 < Sl; k0 += 16) {
        {
            int kk = tid % 16, mm = tid / 16;
            #pragma unroll
            for (int i = 0; i < 4; i++)
                As[kk][mm + 16*i] = A[(size_t)(m0 + mm + 16*i) * Sl + k0 + kk];
        }
        {
            int nn = tid % 64, kk = tid / 64;
            #pragma unroll
            for (int i = 0; i < 4; i++)
                Bs[kk + 4*i][nn] = Bm[(size_t)(k0 + kk + 4*i) * DVn + nn];
        }
        __syncthreads();
        #pragma unroll
        for (int kk = 0; kk < 16; kk++) {
            float4 a = *(const float4*)&As[kk][ty*4];
            float4 b = *(const float4*)&Bs[kk][tx*4];
            float av[4] = {a.x, a.y, a.z, a.w};
            float bv[4] = {b.x, b.y, b.z, b.w};
            #pragma unroll
            for (int i = 0; i < 4; i++)
                #pragma unroll
                for (int j = 0; j < 4; j++)
                    acc[i][j] += av[i] * bv[j];
        }
        __syncthreads();
    }
    int b = z >> 3, h = z & 7;
    #pragma unroll
    for (int i = 0; i < 4; i++) {
        int q = m0 + ty*4 + i;
        #pragma unroll
        for (int j = 0; j < 4; j++) {
            int n = tx*4 + j;               // 0..63
            outp[((size_t)(b * Sl + q)) * (Hn*DVn) + h*64 + n] = acc[i][j];
        }
    }
}

// ---------------- output GEMM: attn[8192,512] @ Wo + bo + x -> seq ----------------
__global__ void gemm_out(const float* __restrict__ A, const float* __restrict__ W,
                         const float* __restrict__ bo, const float* __restrict__ x,
                         float* __restrict__ outp) {
    __shared__ float As[16][68];
    __shared__ float Bs[16][64];
    const int K = Hn * DVn;                 // 512
    int m0 = blockIdx.y * 64;
    int n0 = blockIdx.x * 64;
    int tid = threadIdx.x;
    int tx = tid % 16, ty = tid / 16;
    float acc[4][4] = {};
    for (int k0 = 0; k0 < K; k0 += 16) {
        {
            int kk = tid % 16, mm = tid / 16;
            #pragma unroll
            for (int i = 0; i < 4; i++)
                As[kk][mm + 16*i] = A[(size_t)(m0 + mm + 16*i) * K + k0 + kk];
        }
        {
            int nn = tid % 64, kk = tid / 64;
            #pragma unroll
            for (int i = 0; i < 4; i++)
                Bs[kk + 4*i][nn] = W[(size_t)(k0 + kk + 4*i) * Dm + n0 + nn];
        }
        __syncthreads();
        #pragma unroll
        for (int kk = 0; kk < 16; kk++) {
            float4 a = *(const float4*)&As[kk][ty*4];
            float4 b = *(const float4*)&Bs[kk][tx*4];
            float av[4] = {a.x, a.y, a.z, a.w};
            float bv[4] = {b.x, b.y, b.z, b.w};
            #pragma unroll
            for (int i = 0; i < 4; i++)
                #pragma unroll
                for (int j = 0; j < 4; j++)
                    acc[i][j] += av[i] * bv[j];
        }
        __syncthreads();
    }
    #pragma unroll
    for (int i = 0; i < 4; i++) {
        int m = m0 + ty*4 + i;
        #pragma unroll
        for (int j = 0; j < 4; j++) {
            int n = n0 + tx*4 + j;
            size_t idx = (size_t)m * Dm + n;
            outp[idx] = acc[i][j] + bo[n] + x[idx];
        }
    }
}

// ---------------- launch ----------------
extern "C" void kernel_launch(void* const* d_in, const int* in_sizes, int n_in,
                              void* d_out, int out_size) {
    const float* x   = (const float*)d_in[0];
    const float* lng = (const float*)d_in[1];
    const float* lnb = (const float*)d_in[2];
    const float* Wk  = (const float*)d_in[3];
    const float* bk  = (const float*)d_in[4];
    const float* Wv  = (const float*)d_in[5];
    const float* bv  = (const float*)d_in[6];
    const float* pos = (const float*)d_in[7];
    const float* wp  = (const float*)d_in[8];
    const float* bp  = (const float*)d_in[9];
    const float* Wo  = (const float*)d_in[10];
    const float* bo  = (const float*)d_in[11];
    const int*   lens= (const int*)d_in[12];

    float* out = (float*)d_out;
    const long SEQN  = (long)Bsz * Sl * Dm;        // 4,194,304
    const long PROBN = (long)BH * Sl * Sl;         // 67,108,864

    float *xn, *kq, *vv, *bs, *attn, *seq_fb, *probs_fb;
    cudaGetSymbolAddress((void**)&xn,      g_xn);
    cudaGetSymbolAddress((void**)&kq,      g_k);
    cudaGetSymbolAddress((void**)&vv,      g_v);
    cudaGetSymbolAddress((void**)&bs,      g_bias);
    cudaGetSymbolAddress((void**)&attn,    g_attn);
    cudaGetSymbolAddress((void**)&seq_fb,  g_seq_fb);
    cudaGetSymbolAddress((void**)&probs_fb,g_probs_fb);

    float* seq_out;
    float* probs_out;
    if ((long)out_size >= SEQN + PROBN) { seq_out = out;    probs_out = out + SEQN; }
    else if ((long)out_size == PROBN)   { probs_out = out;  seq_out  = seq_fb;      }
    else                                { seq_out = out;    probs_out = probs_fb;   }

    ln_kernel<<<Bsz * Sl, 128>>>(x, lng, lnb, xn);
    bias_kernel<<<(Sl * Sl) / 256, 256>>>(pos, wp, bp, bs);
    gemm_proj<<<dim3(8, 128), 256>>>(xn, Wk, bk, kq);
    gemm_proj<<<dim3(8, 128), 256>>>(xn, Wv, bv, vv);
    scores_kernel<<<dim3(16, 16, BH), 256>>>(kq, bs, wp, lens, probs_out);
    softmax_kernel<<<BH * Sl, 256>>>(probs_out);
    gemm_pv<<<dim3(1, 16, BH), 256>>>(probs_out, vv, attn);
    gemm_out<<<dim3(8, 128), 256>>>(attn, Wo, bo, x, seq_out);
}

// round 3
// speedup vs baseline: 1.9250x; 1.9250x over previous
#include <cuda_runtime.h>
#include <math.h>
#include <stdint.h>

#define Bsz 8
#define Sl  1024
#define Dm  512
#define Hn  8
#define DQn 64
#define DVn 64
#define Pn  32
#define BH  (Bsz*Hn)   // 64

// ---------------- scratch (__device__ globals: allocation-free) ----------------
__device__ float g_xn  [Bsz*Sl*Dm];            // layernormed x    [8192,512]
__device__ float g_k   [BH*Sl*DQn];            // keys   [B,H,S,DQ]
__device__ float g_v   [BH*Sl*DVn];            // values [B,H,S,DV]
__device__ float g_bias[Sl*Sl];                // (pos@wp + bp)/8  [S,S]
__device__ float g_attn[Bsz*Sl*Hn*DVn];        // attention output [B,S,H*DV]
__device__ float g_seq_fb[Bsz*Sl*Dm];          // fallback seq buffer
__device__ float g_probs_fb[(size_t)BH*Sl*Sl]; // fallback probs buffer

// ================= mma.sync tf32 helpers (arch-feature-free PTX) =================
__device__ __forceinline__ uint32_t f2tf(float f) {
    uint32_t u;
    asm("cvt.rna.tf32.f32 %0, %1;" : "=r"(u) : "f"(f));
    return u;
}
// m16n8k8 tf32: A 4 regs, B 2 regs, C 4 regs (fp32)
__device__ __forceinline__ void mma8(float* c, const uint32_t* a, const uint32_t* b) {
    asm volatile("mma.sync.aligned.m16n8k8.row.col.f32.tf32.tf32.f32 "
        "{%0,%1,%2,%3}, {%4,%5,%6,%7}, {%8,%9}, {%0,%1,%2,%3};"
        : "+f"(c[0]), "+f"(c[1]), "+f"(c[2]), "+f"(c[3])
        : "r"(a[0]), "r"(a[1]), "r"(a[2]), "r"(a[3]), "r"(b[0]), "r"(b[1]));
}

// ---------------- LayerNorm ----------------
__global__ void ln_kernel(const float* __restrict__ x, const float* __restrict__ g,
                          const float* __restrict__ bta, float* __restrict__ xn) {
    __shared__ float rs[4], rs2[4];
    int row = blockIdx.x;
    int tid = threadIdx.x;               // 128 threads, 4 floats each
    const float4* xr = (const float4*)(x + (size_t)row * Dm);
    float4 v = xr[tid];
    float s  = v.x + v.y + v.z + v.w;
    float s2 = v.x*v.x + v.y*v.y + v.z*v.z + v.w*v.w;
    #pragma unroll
    for (int o = 16; o > 0; o >>= 1) {
        s  += __shfl_xor_sync(0xffffffffu, s,  o);
        s2 += __shfl_xor_sync(0xffffffffu, s2, o);
    }
    if ((tid & 31) == 0) { rs[tid >> 5] = s; rs2[tid >> 5] = s2; }
    __syncthreads();
    s  = rs[0]  + rs[1]  + rs[2]  + rs[3];
    s2 = rs2[0] + rs2[1] + rs2[2] + rs2[3];
    float mu  = s * (1.0f / Dm);
    float var = s2 * (1.0f / Dm) - mu * mu;
    float r   = rsqrtf(var + 1e-5f);
    float4 gv = ((const float4*)g)[tid];
    float4 bv = ((const float4*)bta)[tid];
    float4 o;
    o.x = (v.x - mu) * r * gv.x + bv.x;
    o.y = (v.y - mu) * r * gv.y + bv.y;
    o.z = (v.z - mu) * r * gv.z + bv.z;
    o.w = (v.w - mu) * r * gv.w + bv.w;
    ((float4*)(xn + (size_t)row * Dm))[tid] = o;
}

// ---------------- bias = (pos @ wp + bp) / sqrt(DQ) ----------------
__global__ void bias_kernel(const float* __restrict__ pos, const float* __restrict__ wp,
                            const float* __restrict__ bp, float* __restrict__ biasS) {
    __shared__ float w[Pn];
    int tid = threadIdx.x;
    if (tid < Pn) w[tid] = wp[tid];
    __syncthreads();
    int idx = blockIdx.x * blockDim.x + tid;
    const float4* p4 = (const float4*)(pos + (size_t)idx * Pn);
    float acc = 0.f;
    #pragma unroll
    for (int i = 0; i < 8; i++) {
        float4 t = p4[i];
        acc += t.x * w[4*i] + t.y * w[4*i+1] + t.z * w[4*i+2] + t.w * w[4*i+3];
    }
    biasS[idx] = (acc + bp[0]) * 0.125f;
}

// ============ tensor-core GEMM, K=512: A[8192,512] @ B[512,512] ============
// EPI 0: projection -> out[((b*H+h)*S+s)*64+d] = acc + bias[n]
// EPI 1: output     -> out[m*512+n] = acc + bias[n] + resid[m*512+n]
template<int EPI>
__global__ void __launch_bounds__(256) mma_gemm512(
    const float* __restrict__ A, const float* __restrict__ W,
    const float* __restrict__ bias, const float* __restrict__ resid,
    float* __restrict__ outp)
{
    __shared__ uint32_t As[128*36];   // A tile 128 x 32, row stride 36 (bank-clean frags)
    __shared__ uint32_t Bs[32*136];   // B tile 32 x 128, row stride 136
    int tid = threadIdx.x, wid = tid >> 5, lane = tid & 31;
    int gr = lane >> 2, tc = lane & 3;
    int m0 = blockIdx.y * 128, n0 = blockIdx.x * 128;
    int wm = (wid >> 2) * 64, wn = (wid & 3) * 32;
    float c[4][4][4] = {};

    for (int kc = 0; kc < 512; kc += 32) {
        #pragma unroll
        for (int i = 0; i < 4; i++) {                 // A: 128x32 = 1024 float4
            int idx = tid + 256 * i;
            int m = idx >> 3, c4 = idx & 7;
            float4 v = *(const float4*)(A + (size_t)(m0 + m) * 512 + kc + c4 * 4);
            uint32_t* d = &As[m * 36 + c4 * 4];
            d[0] = f2tf(v.x); d[1] = f2tf(v.y); d[2] = f2tf(v.z); d[3] = f2tf(v.w);
        }
        #pragma unroll
        for (int i = 0; i < 4; i++) {                 // B: 32x128 = 1024 float4
            int idx = tid + 256 * i;
            int k = idx >> 5, c4 = idx & 31;
            float4 v = *(const float4*)(W + (size_t)(kc + k) * 512 + n0 + c4 * 4);
            uint32_t* d = &Bs[k * 136 + c4 * 4];
            d[0] = f2tf(v.x); d[1] = f2tf(v.y); d[2] = f2tf(v.z); d[3] = f2tf(v.w);
        }
        __syncthreads();
        #pragma unroll
        for (int ks = 0; ks < 32; ks += 8) {
            uint32_t a[4][4], b[4][2];
            #pragma unroll
            for (int mt = 0; mt < 4; mt++) {
                int m = wm + 16 * mt + gr;
                a[mt][0] = As[m * 36 + ks + tc];
                a[mt][1] = As[(m + 8) * 36 + ks + tc];
                a[mt][2] = As[m * 36 + ks + tc + 4];
                a[mt][3] = As[(m + 8) * 36 + ks + tc + 4];
            }
            #pragma unroll
            for (int nt = 0; nt < 4; nt++) {
                int n = wn + 8 * nt + gr;
                b[nt][0] = Bs[(ks + tc) * 136 + n];
                b[nt][1] = Bs[(ks + tc + 4) * 136 + n];
            }
            #pragma unroll
            for (int mt = 0; mt < 4; mt++)
                #pragma unroll
                for (int nt = 0; nt < 4; nt++)
                    mma8(c[mt][nt], a[mt], b[nt]);
        }
        __syncthreads();
    }
    #pragma unroll
    for (int mt = 0; mt < 4; mt++) {
        #pragma unroll
        for (int half = 0; half < 2; half++) {
            int m = m0 + wm + 16 * mt + gr + 8 * half;
            #pragma unroll
            for (int nt = 0; nt < 4; nt++) {
                int n = n0 + wn + 8 * nt + 2 * tc;
                float2 o;
                o.x = c[mt][nt][2 * half + 0] + bias[n];
                o.y = c[mt][nt][2 * half + 1] + bias[n + 1];
                if (EPI == 0) {
                    int bb = m >> 10, ss = m & 1023, hh = n >> 6, dd = n & 63;
                    *(float2*)&outp[(((size_t)(bb * Hn + hh) * Sl + ss) << 6) + dd] = o;
                } else {
                    size_t idx = (size_t)m * 512 + n;
                    o.x += resid[idx];
                    o.y += resid[idx + 1];
                    *(float2*)&outp[idx] = o;
                }
            }
        }
    }
}

// ============ scores: logits = (Kq . Kk^T)*c1 + bias, masked (tensor core) ============
// grid (8, 8, 64), 256 threads
__global__ void __launch_bounds__(256) scores_mma(
    const float* __restrict__ Kmat, const float* __restrict__ biasS,
    const float* __restrict__ wp, const int* __restrict__ lens,
    float* __restrict__ probs)
{
    __shared__ uint32_t As[128*36];
    __shared__ uint32_t Bs[32*136];
    __shared__ float c1s;
    int tid = threadIdx.x, wid = tid >> 5, lane = tid & 31;
    int gr = lane >> 2, tc = lane & 3;
    int z = blockIdx.z, q0 = blockIdx.y * 128, k0 = blockIdx.x * 128;
    int wm = (wid >> 2) * 64, wn = (wid & 3) * 32;
    const float* Kz = Kmat + (size_t)z * Sl * DQn;
    if (tid == 0) {
        float sw = 0.f;
        #pragma unroll
        for (int i = 0; i < Pn; i++) sw += wp[i];
        c1s = sw * (1.0f / (2.8284271247461903f * 8.0f));   // /(sqrt(H)*sqrt(DQ))
    }
    float c[4][4][4] = {};

    for (int kc = 0; kc < 64; kc += 32) {
        #pragma unroll
        for (int i = 0; i < 4; i++) {                 // A: Kq rows
            int idx = tid + 256 * i;
            int m = idx >> 3, c4 = idx & 7;
            float4 v = *(const float4*)(Kz + (size_t)(q0 + m) * 64 + kc + c4 * 4);
            uint32_t* d = &As[m * 36 + c4 * 4];
            d[0] = f2tf(v.x); d[1] = f2tf(v.y); d[2] = f2tf(v.z); d[3] = f2tf(v.w);
        }
        #pragma unroll
        for (int i = 0; i < 4; i++) {                 // B: Kk transposed -> Bs[d][key]
            int idx = tid + 256 * i;
            int key = idx >> 3, c4 = idx & 7;
            float4 v = *(const float4*)(Kz + (size_t)(k0 + key) * 64 + kc + c4 * 4);
            Bs[(c4 * 4 + 0) * 136 + key] = f2tf(v.x);
            Bs[(c4 * 4 + 1) * 136 + key] = f2tf(v.y);
            Bs[(c4 * 4 + 2) * 136 + key] = f2tf(v.z);
            Bs[(c4 * 4 + 3) * 136 + key] = f2tf(v.w);
        }
        __syncthreads();
        #pragma unroll
        for (int ks = 0; ks < 32; ks += 8) {
            uint32_t a[4][4], b[4][2];
            #pragma unroll
            for (int mt = 0; mt < 4; mt++) {
                int m = wm + 16 * mt + gr;
                a[mt][0] = As[m * 36 + ks + tc];
                a[mt][1] = As[(m + 8) * 36 + ks + tc];
                a[mt][2] = As[m * 36 + ks + tc + 4];
                a[mt][3] = As[(m + 8) * 36 + ks + tc + 4];
            }
            #pragma unroll
            for (int nt = 0; nt < 4; nt++) {
                int n = wn + 8 * nt + gr;
                b[nt][0] = Bs[(ks + tc) * 136 + n];
                b[nt][1] = Bs[(ks + tc + 4) * 136 + n];
            }
            #pragma unroll
            for (int mt = 0; mt < 4; mt++)
                #pragma unroll
                for (int nt = 0; nt < 4; nt++)
                    mma8(c[mt][nt], a[mt], b[nt]);
        }
        __syncthreads();
    }

    float c1 = c1s;
    int len = lens[z >> 3];
    #pragma unroll
    for (int mt = 0; mt < 4; mt++) {
        #pragma unroll
        for (int half = 0; half < 2; half++) {
            int q = q0 + wm + 16 * mt + gr + 8 * half;
            const float* brow = biasS + (size_t)q * Sl;
            float* prow = probs + ((size_t)z * Sl + q) * Sl;
            #pragma unroll
            for (int nt = 0; nt < 4; nt++) {
                int kk = k0 + wn + 8 * nt + 2 * tc;
                float2 bb = *(const float2*)(brow + kk);
                float2 o;
                o.x = (kk     < len) ? c[mt][nt][2 * half + 0] * c1 + bb.x : -INFINITY;
                o.y = (kk + 1 < len) ? c[mt][nt][2 * half + 1] * c1 + bb.y : -INFINITY;
                *(float2*)(prow + kk) = o;
            }
        }
    }
}

// ============ PV: attn = probs @ V (tensor core), per head ============
// grid (8, 64), 256 threads; warp tile 32x32, block tile 128x64
__global__ void __launch_bounds__(256) pv_mma(
    const float* __restrict__ probs, const float* __restrict__ V,
    float* __restrict__ attn)
{
    __shared__ uint32_t As[128*36];   // probs chunk 128 x 32
    __shared__ uint32_t Bs[32*72];    // v chunk 32 x 64
    int tid = threadIdx.x, wid = tid >> 5, lane = tid & 31;
    int gr = lane >> 2, tc = lane & 3;
    int z = blockIdx.y, q0 = blockIdx.x * 128;
    int wm = (wid >> 1) * 32, wn = (wid & 1) * 32;
    const float* Az = probs + (size_t)z * Sl * Sl;
    const float* Bz = V + (size_t)z * Sl * DVn;
    float c[2][4][4] = {};

    for (int kc = 0; kc < Sl; kc += 32) {
        #pragma unroll
        for (int i = 0; i < 4; i++) {                 // A: 128x32
            int idx = tid + 256 * i;
            int m = idx >> 3, c4 = idx & 7;
            float4 v = *(const float4*)(Az + (size_t)(q0 + m) * Sl + kc + c4 * 4);
            uint32_t* d = &As[m * 36 + c4 * 4];
            d[0] = f2tf(v.x); d[1] = f2tf(v.y); d[2] = f2tf(v.z); d[3] = f2tf(v.w);
        }
        #pragma unroll
        for (int i = 0; i < 2; i++) {                 // B: 32x64
            int idx = tid + 256 * i;
            int k = idx >> 4, c4 = idx & 15;
            float4 v = *(const float4*)(Bz + (size_t)(kc + k) * 64 + c4 * 4);
            uint32_t* d = &Bs[k * 72 + c4 * 4];
            d[0] = f2tf(v.x); d[1] = f2tf(v.y); d[2] = f2tf(v.z); d[3] = f2tf(v.w);
        }
        __syncthreads();
        #pragma unroll
        for (int ks = 0; ks < 32; ks += 8) {
            uint32_t a[2][4], b[4][2];
            #pragma unroll
            for (int mt = 0; mt < 2; mt++) {
                int m = wm + 16 * mt + gr;
                a[mt][0] = As[m * 36 + ks + tc];
                a[mt][1] = As[(m + 8) * 36 + ks + tc];
                a[mt][2] = As[m * 36 + ks + tc + 4];
                a[mt][3] = As[(m + 8) * 36 + ks + tc + 4];
            }
            #pragma unroll
            for (int nt = 0; nt < 4; nt++) {
                int n = wn + 8 * nt + gr;
                b[nt][0] = Bs[(ks + tc) * 72 + n];
                b[nt][1] = Bs[(ks + tc + 4) * 72 + n];
            }
            #pragma unroll
            for (int mt = 0; mt < 2; mt++)
                #pragma unroll
                for (int nt = 0; nt < 4; nt++)
                    mma8(c[mt][nt], a[mt], b[nt]);
        }
        __syncthreads();
    }

    int b = z >> 3, h = z & 7;
    #pragma unroll
    for (int mt = 0; mt < 2; mt++) {
        #pragma unroll
        for (int half = 0; half < 2; half++) {
            int q = q0 + wm + 16 * mt + gr + 8 * half;
            float* orow = attn + ((size_t)(b * Sl + q)) * (Hn * DVn) + h * 64;
            #pragma unroll
            for (int nt = 0; nt < 4; nt++) {
                int n = wn + 8 * nt + 2 * tc;
                float2 o;
                o.x = c[mt][nt][2 * half + 0];
                o.y = c[mt][nt][2 * half + 1];
                *(float2*)(orow + n) = o;
            }
        }
    }
}

// ---------------- in-place row softmax ----------------
__global__ void softmax_kernel(float* __restrict__ probs) {
    __shared__ float red[8];
    size_t row = blockIdx.x;
    float* p = probs + row * Sl;
    int tid = threadIdx.x;
    float4 v = ((const float4*)p)[tid];
    float m = fmaxf(fmaxf(v.x, v.y), fmaxf(v.z, v.w));
    #pragma unroll
    for (int o = 16; o > 0; o >>= 1) m = fmaxf(m, __shfl_xor_sync(0xffffffffu, m, o));
    if ((tid & 31) == 0) red[tid >> 5] = m;
    __syncthreads();
    m = red[0];
    #pragma unroll
    for (int i = 1; i < 8; i++) m = fmaxf(m, red[i]);
    float4 e;
    e.x = expf(v.x - m); e.y = expf(v.y - m);
    e.z = expf(v.z - m); e.w = expf(v.w - m);
    float s = e.x + e.y + e.z + e.w;
    #pragma unroll
    for (int o = 16; o > 0; o >>= 1) s += __shfl_xor_sync(0xffffffffu, s, o);
    __syncthreads();
    if ((tid & 31) == 0) red[tid >> 5] = s;
    __syncthreads();
    float tot = red[0];
    #pragma unroll
    for (int i = 1; i < 8; i++) tot += red[i];
    float inv = 1.0f / tot;
    ((float4*)p)[tid] = make_float4(e.x * inv, e.y * inv, e.z * inv, e.w * inv);
}

// ---------------- launch ----------------
extern "C" void kernel_launch(void* const* d_in, const int* in_sizes, int n_in,
                              void* d_out, int out_size) {
    const float* x   = (const float*)d_in[0];
    const float* lng = (const float*)d_in[1];
    const float* lnb = (const float*)d_in[2];
    const float* Wk  = (const float*)d_in[3];
    const float* bk  = (const float*)d_in[4];
    const float* Wv  = (const float*)d_in[5];
    const float* bv  = (const float*)d_in[6];
    const float* pos = (const float*)d_in[7];
    const float* wp  = (const float*)d_in[8];
    const float* bp  = (const float*)d_in[9];
    const float* Wo  = (const float*)d_in[10];
    const float* bo  = (const float*)d_in[11];
    const int*   lens= (const int*)d_in[12];

    float* out = (float*)d_out;
    const long SEQN  = (long)Bsz * Sl * Dm;
    const long PROBN = (long)BH * Sl * Sl;

    float *xn, *kq, *vv, *bs, *attn, *seq_fb, *probs_fb;
    cudaGetSymbolAddress((void**)&xn,       g_xn);
    cudaGetSymbolAddress((void**)&kq,       g_k);
    cudaGetSymbolAddress((void**)&vv,       g_v);
    cudaGetSymbolAddress((void**)&bs,       g_bias);
    cudaGetSymbolAddress((void**)&attn,     g_attn);
    cudaGetSymbolAddress((void**)&seq_fb,   g_seq_fb);
    cudaGetSymbolAddress((void**)&probs_fb, g_probs_fb);

    float* seq_out;
    float* probs_out;
    if ((long)out_size >= SEQN + PROBN) { seq_out = out;    probs_out = out + SEQN; }
    else if ((long)out_size == PROBN)   { probs_out = out;  seq_out  = seq_fb;      }
    else                                { seq_out = out;    probs_out = probs_fb;   }

    ln_kernel<<<Bsz * Sl, 128>>>(x, lng, lnb, xn);
    bias_kernel<<<(Sl * Sl) / 256, 256>>>(pos, wp, bp, bs);
    mma_gemm512<0><<<dim3(4, 64), 256>>>(xn, Wk, bk, nullptr, kq);
    mma_gemm512<0><<<dim3(4, 64), 256>>>(xn, Wv, bv, nullptr, vv);
    scores_mma<<<dim3(8, 8, BH), 256>>>(kq, bs, wp, lens, probs_out);
    softmax_kernel<<<BH * Sl, 256>>>(probs_out);
    pv_mma<<<dim3(8, BH), 256>>>(probs_out, vv, attn);
    mma_gemm512<1><<<dim3(4, 64), 256>>>(attn, Wo, bo, x, seq_out);
}